// round 2
// baseline (speedup 1.0000x reference)
#include <cuda_runtime.h>

#define N_GENES 20000
#define UNITS   10000
#define DEG     32
#define BATCH   128

// Scratch: |feature| transposed to [gene][batch] so each gather reads a
// contiguous 512B row. 10.24 MB — L2-resident on GB300.
__device__ float g_featT[(size_t)N_GENES * BATCH];

// ---------------------------------------------------------------------------
// K1: tiled transpose + fabs.  feature [B=128, N=20000] -> g_featT [N, B]
// ---------------------------------------------------------------------------
__global__ void transpose_abs_kernel(const float* __restrict__ feature) {
    __shared__ float tile[32][33];
    const int gx = blockIdx.x * 32;   // gene base
    const int bx = blockIdx.y * 32;   // batch base
    const int tx = threadIdx.x, ty = threadIdx.y;

#pragma unroll
    for (int k = 0; k < 32; k += 8) {
        tile[ty + k][tx] = fabsf(feature[(size_t)(bx + ty + k) * N_GENES + (gx + tx)]);
    }
    __syncthreads();
#pragma unroll
    for (int k = 0; k < 32; k += 8) {
        g_featT[(size_t)(gx + ty + k) * BATCH + (bx + tx)] = tile[tx][ty + k];
    }
}

// ---------------------------------------------------------------------------
// K2: gather-sum. One warp handles a unit: lane d owns ppi[u][d]; broadcast
// index via shfl; each lane loads float4 (4 batch rows) from featT row.
// 32 units per CTA, staged in smem, coalesced store to [B, U] output.
// ---------------------------------------------------------------------------
__global__ void __launch_bounds__(256) ppi_gather_kernel(
    const int*   __restrict__ ppi,     // int32! (JAX x64-disabled downgrades int64)
    const float* __restrict__ kern,
    const float* __restrict__ bias,
    float*       __restrict__ out)
{
    // +4 pad keeps rows 16B-aligned (132 floats = 528B) and breaks the
    // stride-128 bank pattern in the epilogue reads.
    __shared__ float tile[32][BATCH + 4];

    const int lane   = threadIdx.x & 31;
    const int warp   = threadIdx.x >> 5;           // 0..7
    const int u_base = blockIdx.x * 32;

#pragma unroll
    for (int j = 0; j < 4; j++) {
        const int u_local = warp * 4 + j;
        const int u = u_base + u_local;
        if (u < UNITS) {
            // lane d holds index d of this unit (coalesced 128B i32 load)
            const int myidx = ppi[(size_t)u * DEG + lane];

            float4 acc = make_float4(0.f, 0.f, 0.f, 0.f);
#pragma unroll
            for (int d = 0; d < DEG; d++) {
                const int g = __shfl_sync(0xffffffffu, myidx, d);
                const float4 v = *(const float4*)&g_featT[(size_t)g * BATCH + lane * 4];
                acc.x += v.x; acc.y += v.y; acc.z += v.z; acc.w += v.w;
            }
            const float kv = kern[u];
            const float bv = bias[u];
            float4 r;
            r.x = tanhf(fmaf(acc.x, kv, bv));
            r.y = tanhf(fmaf(acc.y, kv, bv));
            r.z = tanhf(fmaf(acc.z, kv, bv));
            r.w = tanhf(fmaf(acc.w, kv, bv));
            // contiguous 512B row store per warp — conflict-free
            *(float4*)&tile[u_local][lane * 4] = r;
        }
    }
    __syncthreads();

    // Coalesced epilogue: consecutive threads -> consecutive units, so each
    // group of 32 threads writes a contiguous 128B chunk of one batch row.
    const int n_valid = min(32, UNITS - u_base);
    for (int t = threadIdx.x; t < BATCH * 32; t += 256) {
        const int u_l = t & 31;
        const int b   = t >> 5;
        if (u_l < n_valid)
            out[(size_t)b * UNITS + (u_base + u_l)] = tile[u_l][b];
    }
}

// ---------------------------------------------------------------------------
extern "C" void kernel_launch(void* const* d_in, const int* in_sizes, int n_in,
                              void* d_out, int out_size) {
    const float* feature = (const float*)d_in[0];
    const int*   ppi     = (const int*)d_in[1];
    const float* kern    = (const float*)d_in[2];
    const float* bias    = (const float*)d_in[3];
    float*       out     = (float*)d_out;

    dim3 tgrid(N_GENES / 32, BATCH / 32);   // (625, 4)
    dim3 tblock(32, 8);
    transpose_abs_kernel<<<tgrid, tblock>>>(feature);

    const int n_cta = (UNITS + 31) / 32;    // 313
    ppi_gather_kernel<<<n_cta, 256>>>(ppi, kern, bias, out);
}

// round 3
// speedup vs baseline: 1.3877x; 1.3877x over previous
#include <cuda_runtime.h>
#include <cuda_fp16.h>

#define N_GENES 20000
#define UNITS   10000
#define DEG     32
#define BATCH   128

// |feature| transposed to [gene][batch] in fp16: 5.12 MB, L2-resident.
// Each (unit, deg) gather reads one 256B contiguous row.
__device__ __half g_featT[(size_t)N_GENES * BATCH];

// ---------------------------------------------------------------------------
// K1: tiled transpose + fabs + fp16 convert.  feature [128, 20000] -> [N, B]
// ---------------------------------------------------------------------------
__global__ void transpose_abs_kernel(const float* __restrict__ feature) {
    __shared__ float tile[32][33];
    const int gx = blockIdx.x * 32;   // gene base
    const int bx = blockIdx.y * 32;   // batch base
    const int tx = threadIdx.x, ty = threadIdx.y;

#pragma unroll
    for (int k = 0; k < 32; k += 8) {
        tile[ty + k][tx] = fabsf(feature[(size_t)(bx + ty + k) * N_GENES + (gx + tx)]);
    }
    __syncthreads();
#pragma unroll
    for (int k = 0; k < 32; k += 8) {
        g_featT[(size_t)(gx + ty + k) * BATCH + (bx + tx)] =
            __float2half(tile[tx][ty + k]);
    }
}

// ---------------------------------------------------------------------------
// K2: gather-sum. One warp per unit: lane d holds ppi[u][d]; broadcast via
// shfl; each lane loads 4 halves (4 batch rows) -> fp32 accumulate.
// 8 units per CTA (grid=1250 for occupancy), smem-staged coalesced output.
// ---------------------------------------------------------------------------
__global__ void __launch_bounds__(256) ppi_gather_kernel(
    const int*   __restrict__ ppi,     // int32 (JAX x64-disabled)
    const float* __restrict__ kern,
    const float* __restrict__ bias,
    float*       __restrict__ out)
{
    __shared__ float tile[8][BATCH + 4];

    const int lane   = threadIdx.x & 31;
    const int warp   = threadIdx.x >> 5;          // 0..7
    const int u_base = blockIdx.x * 8;
    const int u      = u_base + warp;             // grid covers UNITS exactly

    // lane d owns index d of this unit (coalesced 128B i32 load per warp)
    const int myidx = ppi[(size_t)u * DEG + lane];

    float4 acc = make_float4(0.f, 0.f, 0.f, 0.f);
#pragma unroll
    for (int d = 0; d < DEG; d++) {
        const int g = __shfl_sync(0xffffffffu, myidx, d);
        const uint2 raw = *(const uint2*)&g_featT[(size_t)g * BATCH + lane * 4];
        const float2 f01 = __half22float2(*(const __half2*)&raw.x);
        const float2 f23 = __half22float2(*(const __half2*)&raw.y);
        acc.x += f01.x; acc.y += f01.y; acc.z += f23.x; acc.w += f23.y;
    }

    const float kv = kern[u];
    const float bv = bias[u];
    float4 r;
    r.x = tanhf(fmaf(acc.x, kv, bv));
    r.y = tanhf(fmaf(acc.y, kv, bv));
    r.z = tanhf(fmaf(acc.z, kv, bv));
    r.w = tanhf(fmaf(acc.w, kv, bv));
    *(float4*)&tile[warp][lane * 4] = r;

    __syncthreads();

    // Coalesced epilogue: consecutive threads -> consecutive units, each
    // 8-thread group writes a contiguous 32B chunk of one batch row.
    // Bank-conflict-free smem reads (132-float row stride).
    for (int t = threadIdx.x; t < BATCH * 8; t += 256) {
        const int u_l = t & 7;
        const int b   = t >> 3;
        out[(size_t)b * UNITS + (u_base + u_l)] = tile[u_l][b];
    }
}

// ---------------------------------------------------------------------------
extern "C" void kernel_launch(void* const* d_in, const int* in_sizes, int n_in,
                              void* d_out, int out_size) {
    const float* feature = (const float*)d_in[0];
    const int*   ppi     = (const int*)d_in[1];
    const float* kern    = (const float*)d_in[2];
    const float* bias    = (const float*)d_in[3];
    float*       out     = (float*)d_out;

    dim3 tgrid(N_GENES / 32, BATCH / 32);   // (625, 4)
    dim3 tblock(32, 8);
    transpose_abs_kernel<<<tgrid, tblock>>>(feature);

    ppi_gather_kernel<<<UNITS / 8, 256>>>(ppi, kern, bias, out);  // 1250 CTAs
}